// round 16
// baseline (speedup 1.0000x reference)
#include <cuda_runtime.h>
#include <cuda_bf16.h>
#include <cuda_fp16.h>
#include <cstdint>

// ---------------- Problem constants ----------------
#define B_     16384
#define F_     26
#define V_     100000
#define E_     16
#define CONT_  13
#define K1_    429     // CONT_ + F_*E_
#define KP_    448     // padded K for BOTH GEMMs (mult of 64)
#define H_     400
#define NT_    80      // CTA N tile (5 * 80 = 400, exact)

// dnn_in layout (KP_): [ emb 0..415 | cont 416..428 | zero 429..447 ]
// h1 layout (KP_):     [ h1 0..399 | zero 400..447 ]  (pad never written; zero-init)

// ---------------- Scratch (device globals) ----------------
__device__ __align__(256) __half g_dnn [(size_t)B_ * KP_];
__device__ __align__(256) __half g_h1  [(size_t)B_ * KP_];
__device__ __align__(256) __half g_w1t [(size_t)H_ * KP_];
__device__ __align__(256) __half g_w2t [(size_t)H_ * KP_];
__device__ float g_fm  [B_];
__device__ float g_part[5][B_];
__device__ int   g_gath[B_ / 128];      // gather->GEMM1 tile readiness (self-reset)
__device__ int   g_cnt1[B_ / 128];      // GEMM1->GEMM2 tile readiness (self-reset)
__device__ int   g_cnt [B_ / 128];      // GEMM2 finish counter (self-reset)

// ---------------- PTX helpers ----------------
__device__ __forceinline__ uint32_t smem_u32(const void* p) {
    return (uint32_t)__cvta_generic_to_shared(p);
}
__device__ __forceinline__ int ld_acquire(const int* p) {
    int v;
    asm volatile("ld.acquire.gpu.global.s32 %0, [%1];" : "=r"(v) : "l"(p));
    return v;
}
#define CP16(dst_u32, src) \
    asm volatile("cp.async.cg.shared.global [%0], [%1], 16;" :: "r"(dst_u32), "l"(src))
#define CP_COMMIT() asm volatile("cp.async.commit_group;" ::: "memory")
#define CP_WAIT0()  asm volatile("cp.async.wait_group 0;" ::: "memory")
#define CP_WAIT1()  asm volatile("cp.async.wait_group 1;" ::: "memory")

#define LDSM_X4(r0, r1, r2, r3, addr)                                          \
    asm volatile("ldmatrix.sync.aligned.m8n8.x4.shared.b16 {%0,%1,%2,%3},[%4];"\
                 : "=r"(r0), "=r"(r1), "=r"(r2), "=r"(r3) : "r"(addr))
#define LDSM_X2(r0, r1, addr)                                                  \
    asm volatile("ldmatrix.sync.aligned.m8n8.x2.shared.b16 {%0,%1},[%2];"      \
                 : "=r"(r0), "=r"(r1) : "r"(addr))

__device__ __forceinline__ void mma_fp16(float* c,
                                         uint32_t a0, uint32_t a1, uint32_t a2, uint32_t a3,
                                         uint32_t b0, uint32_t b1) {
    asm volatile(
        "mma.sync.aligned.m16n8k16.row.col.f32.f16.f16.f32 "
        "{%0,%1,%2,%3},{%4,%5,%6,%7},{%8,%9},{%0,%1,%2,%3};"
        : "+f"(c[0]), "+f"(c[1]), "+f"(c[2]), "+f"(c[3])
        : "r"(a0), "r"(a1), "r"(a2), "r"(a3), "r"(b0), "r"(b1));
}

// ============================================================================
// Prep (launch 1): tiled 32x32 smem transpose, coalesced read AND write.
//   blocks 0..181: W1 (with dnn-layout k-permutation); 182..363: W2.
// ============================================================================
#define KTILES_ 14   // 448/32
#define NTILES_ 13   // ceil(400/32)
#define PREP_BLKS (2 * KTILES_ * NTILES_)   // 364

__global__ void __launch_bounds__(128)
prep_kernel(const float* __restrict__ W1, const float* __restrict__ W2) {
    __shared__ float sm[32][33];
    int t = blockIdx.x;
    const bool m2 = (t >= KTILES_ * NTILES_);
    if (m2) t -= KTILES_ * NTILES_;
    const int kt = t % KTILES_, nt = t / KTILES_;
    const int tx = threadIdx.x & 31, ty = threadIdx.x >> 5;   // 32 x 4

    #pragma unroll
    for (int i = 0; i < 8; i++) {
        int k = kt * 32 + ty + i * 4;      // global padded-k
        int n = nt * 32 + tx;              // global n
        float v = 0.f;
        if (n < H_) {
            if (!m2) {
                if (k < 416)      v = W1[(size_t)(CONT_ + k) * H_ + n];
                else if (k < 429) v = W1[(size_t)(k - 416) * H_ + n];
            } else {
                if (k < H_)       v = W2[(size_t)k * H_ + n];
            }
        }
        sm[ty + i * 4][tx] = v;
    }
    __syncthreads();
    __half* dst = m2 ? g_w2t : g_w1t;
    #pragma unroll
    for (int i = 0; i < 8; i++) {
        int n = nt * 32 + ty + i * 4;
        int k = kt * 32 + tx;
        if (n < H_)
            dst[(size_t)n * KP_ + k] = __float2half_rn(sm[tx][ty + i * 4]);
    }
}

// ============================================================================
// Megakernel (launch 2): 5376 CTAs, 128 threads each.
//   bids [0,4096)      : gather+FM, 4 warps = 4 samples; increments g_gath.
//   bids [4096,4736)   : GEMM1 (waits g_gath[by]==32): h1 = relu(dnn@W1+b1).
//   bids [4736,5376)   : GEMM2 (waits g_cnt1[by]==5): dot w/ Wout; finisher
//                        writes out and resets this tile's counters.
//   GEMM geometry: CTA 128x80, 4 warps, warp tile 64x40, BK=64, K=448.
// ============================================================================
#define ROWB_   144
#define OFFB_   (128 * ROWB_)
#define STAGE_  ((128 + NT_) * ROWB_)    // 29952
#define NKB_    7
#define GA_BLKS (B_ / 4)                 // 4096
#define G1_OFF  GA_BLKS                  // 4096
#define G2_OFF  (GA_BLKS + 5 * (B_ / 128))   // 4736
#define ALL_BLKS (GA_BLKS + 10 * (B_ / 128)) // 5376

__global__ void __launch_bounds__(128)
megakernel(const float* __restrict__ cont, const int* __restrict__ cat,
           const float* __restrict__ w_cont, const float* __restrict__ b_cont,
           const float* __restrict__ t_first, const float* __restrict__ t_emb,
           const float* __restrict__ b1, const float* __restrict__ b2,
           const float* __restrict__ Wout, const float* __restrict__ bout,
           float* __restrict__ out) {
    constexpr int CPR = 8;
    constexpr int NCH = (128 + NT_) * CPR;   // 1664
    constexpr int NIT = NCH / 128;           // 13

    extern __shared__ char smem_raw[];
    __shared__ float part[2][128];
    __shared__ float smfm[4][F_][17];
    __shared__ int   s_done;

    const int bid = blockIdx.x;
    const int tid = threadIdx.x;

    // ========================= GATHER region =========================
    if (bid < GA_BLKS) {
        int wid  = tid >> 5;
        int lane = tid & 31;
        const int b = bid * 4 + wid;
        float scal = 0.f;

        if (lane < F_) {
            int idx = cat[b * F_ + lane];
            const float4* row =
                reinterpret_cast<const float4*>(t_emb + ((size_t)lane * V_ + (size_t)idx) * E_);
            float4 r0 = row[0], r1 = row[1], r2 = row[2], r3 = row[3];
            float v[16] = {r0.x,r0.y,r0.z,r0.w, r1.x,r1.y,r1.z,r1.w,
                           r2.x,r2.y,r2.z,r2.w, r3.x,r3.y,r3.z,r3.w};
            uint32_t pk[8];
            #pragma unroll
            for (int i = 0; i < 8; i++) {
                __half h0 = __float2half_rn(v[2*i]);
                __half h1 = __float2half_rn(v[2*i+1]);
                pk[i] = (uint32_t)__half_as_ushort(h0) |
                        ((uint32_t)__half_as_ushort(h1) << 16);
            }
            uint4* dst = reinterpret_cast<uint4*>(g_dnn + (size_t)b * KP_ + lane * E_);
            dst[0] = make_uint4(pk[0], pk[1], pk[2], pk[3]);
            dst[1] = make_uint4(pk[4], pk[5], pk[6], pk[7]);
            #pragma unroll
            for (int e = 0; e < 16; e++) smfm[wid][lane][e] = v[e];
            scal = t_first[(size_t)lane * V_ + (size_t)idx];
        }
        if (lane < CONT_) {
            float c = cont[b * CONT_ + lane];
            g_dnn[(size_t)b * KP_ + 416 + lane] = __float2half_rn(c);
            scal = fmaf(c, w_cont[lane], scal);
        }
        if (lane < KP_ - K1_) {
            g_dnn[(size_t)b * KP_ + K1_ + lane] = __ushort_as_half((unsigned short)0);
        }
        __syncwarp();

        float pe = 0.f;
        if (lane < 16) {
            float S = 0.f, qe = 0.f;
            #pragma unroll
            for (int f = 0; f < F_; f++) {
                float x = smfm[wid][f][lane];
                S += x;
                qe = fmaf(x, x, qe);
            }
            pe = fmaf(S, S, -qe);
        }
        #pragma unroll
        for (int off = 16; off; off >>= 1) {
            pe   += __shfl_xor_sync(0xffffffffu, pe,   off);
            scal += __shfl_xor_sync(0xffffffffu, scal, off);
        }
        if (lane == 0) g_fm[b] = scal + b_cont[0] + 0.5f * pe;

        __threadfence();
        __syncthreads();
        if (tid == 0) atomicAdd(&g_gath[bid >> 5], 1);   // 32 blocks per M-tile
        return;
    }

    // ========================= GEMM region =========================
    const bool p2  = (bid >= G2_OFF);
    const int lbid = p2 ? bid - G2_OFF : bid - G1_OFF;
    const int by   = lbid / 5;
    const int bx   = lbid % 5;

    const __half* A    = p2 ? g_h1 : g_dnn;
    const __half* Bw   = p2 ? g_w2t : g_w1t;
    const float*  bias = p2 ? b2  : b1;

    const uint32_t sbase = smem_u32(smem_raw);
    const int warp = tid >> 5, lane = tid & 31;
    const int gr = lane >> 2, gc = lane & 3;
    const int wm  = (warp >> 1) * 64;
    const int wni = warp & 1;
    const int wn  = wni * 40;
    const int m0 = by * 128;
    const int n0 = bx * NT_;

    const int lane8 = lane & 7;
    const int laneH = (lane >> 3) & 1;
    const int laneK = lane >> 4;
    const uint32_t aoff  = (uint32_t)((wm + lane8 + laneH * 8) * ROWB_ + laneK * 16);
    const uint32_t boff4 = (uint32_t)((wn + lane8 + laneK * 8) * ROWB_ + laneH * 16);
    const uint32_t boff2 = (uint32_t)((wn + 32 + lane8) * ROWB_ + laneH * 16);

    // dependency wait
    if (tid == 0) {
        if (p2) { while (ld_acquire(&g_cnt1[by]) != 5)  __nanosleep(64); }
        else    { while (ld_acquire(&g_gath[by]) != 32) __nanosleep(64); }
    }
    __syncthreads();

    float acc[4][5][4];
    #pragma unroll
    for (int i = 0; i < 4; i++)
        #pragma unroll
        for (int j = 0; j < 5; j++)
            #pragma unroll
            for (int k = 0; k < 4; k++) acc[i][j][k] = 0.f;

    #define LOAD_KB(KB, BUF)                                                        \
    do {                                                                            \
        const int k0_ = (KB) * 64;                                                  \
        const uint32_t st_ = sbase + (BUF) * STAGE_;                                \
        _Pragma("unroll")                                                           \
        for (int h = 0; h < NIT; h++) {                                             \
            int c_ = tid + h * 128;                                                 \
            int row_ = c_ / CPR, q_ = c_ % CPR;                                     \
            if (row_ < 128) {                                                       \
                CP16(st_ + row_ * ROWB_ + q_ * 16,                                  \
                     A + (size_t)(m0 + row_) * KP_ + k0_ + q_ * 8);                 \
            } else {                                                                \
                int r2_ = row_ - 128;                                               \
                CP16(st_ + OFFB_ + r2_ * ROWB_ + q_ * 16,                           \
                     Bw + (size_t)(n0 + r2_) * KP_ + k0_ + q_ * 8);                 \
            }                                                                       \
        }                                                                           \
    } while (0)

    LOAD_KB(0, 0);
    CP_COMMIT();

    for (int kb = 0; kb < NKB_; kb++) {
        const int buf = kb & 1;
        if (kb + 1 < NKB_) { LOAD_KB(kb + 1, buf ^ 1); CP_COMMIT(); CP_WAIT1(); }
        else               { CP_WAIT0(); }
        __syncthreads();

        const uint32_t st = sbase + buf * STAGE_;
        #pragma unroll
        for (int ks = 0; ks < 4; ks++) {
            const uint32_t ko = ks * 32;
            uint32_t ah[4][4], bh[5][2];
            #pragma unroll
            for (int mi = 0; mi < 4; mi++) {
                uint32_t ad = st + aoff + mi * (16 * ROWB_) + ko;
                LDSM_X4(ah[mi][0], ah[mi][1], ah[mi][2], ah[mi][3], ad);
            }
            #pragma unroll
            for (int nj = 0; nj < 2; nj++) {
                uint32_t bd = st + OFFB_ + boff4 + nj * (16 * ROWB_) + ko;
                LDSM_X4(bh[nj*2][0], bh[nj*2][1], bh[nj*2+1][0], bh[nj*2+1][1], bd);
            }
            LDSM_X2(bh[4][0], bh[4][1], st + OFFB_ + boff2 + ko);

            #pragma unroll
            for (int mi = 0; mi < 4; mi++)
                #pragma unroll
                for (int ni = 0; ni < 5; ni++)
                    mma_fp16(acc[mi][ni], ah[mi][0], ah[mi][1], ah[mi][2], ah[mi][3],
                             bh[ni][0], bh[ni][1]);
        }
        __syncthreads();
    }
    #undef LOAD_KB

    if (!p2) {
        // ---- GEMM1 epilogue: relu(+bias) -> h1 fp16 ----
        #pragma unroll
        for (int mi = 0; mi < 4; mi++) {
            int r = m0 + wm + mi * 16 + gr;
            #pragma unroll
            for (int ni = 0; ni < 5; ni++) {
                int n = n0 + wn + ni * 8 + gc * 2;
                float b0v = bias[n], b1v = bias[n + 1];
                #pragma unroll
                for (int half = 0; half < 2; half++) {
                    float x0 = fmaxf(acc[mi][ni][half * 2 + 0] + b0v, 0.f);
                    float x1 = fmaxf(acc[mi][ni][half * 2 + 1] + b1v, 0.f);
                    __half h0 = __float2half_rn(x0);
                    __half h1 = __float2half_rn(x1);
                    uint32_t ph = (uint32_t)__half_as_ushort(h0) |
                                  ((uint32_t)__half_as_ushort(h1) << 16);
                    size_t o = (size_t)(r + half * 8) * KP_ + n;
                    *reinterpret_cast<uint32_t*>(g_h1 + o) = ph;
                }
            }
        }
        __threadfence();
        __syncthreads();
        if (tid == 0) atomicAdd(&g_cnt1[by], 1);
    } else {
        // ---- GEMM2 epilogue: dot with Wout; finisher writes out ----
        #pragma unroll
        for (int mi = 0; mi < 4; mi++) {
            float s0 = 0.f, s1 = 0.f;
            #pragma unroll
            for (int ni = 0; ni < 5; ni++) {
                int n = n0 + wn + ni * 8 + gc * 2;
                float w0v = Wout[1 + n], w1v = Wout[2 + n];
                float b0v = bias[n],     b1v = bias[n + 1];
                s0 = fmaf(fmaxf(acc[mi][ni][0] + b0v, 0.f), w0v, s0);
                s0 = fmaf(fmaxf(acc[mi][ni][1] + b1v, 0.f), w1v, s0);
                s1 = fmaf(fmaxf(acc[mi][ni][2] + b0v, 0.f), w0v, s1);
                s1 = fmaf(fmaxf(acc[mi][ni][3] + b1v, 0.f), w1v, s1);
            }
            s0 += __shfl_xor_sync(0xffffffffu, s0, 1);
            s0 += __shfl_xor_sync(0xffffffffu, s0, 2);
            s1 += __shfl_xor_sync(0xffffffffu, s1, 1);
            s1 += __shfl_xor_sync(0xffffffffu, s1, 2);
            if (gc == 0) {
                part[wni][wm + mi * 16 + gr]     = s0;
                part[wni][wm + mi * 16 + gr + 8] = s1;
            }
        }
        __syncthreads();
        g_part[bx][m0 + tid] = part[0][tid] + part[1][tid];
        __threadfence();
        __syncthreads();
        if (tid == 0) s_done = atomicAdd(&g_cnt[by], 1);
        __syncthreads();
        if (s_done == 4) {            // last GEMM2 CTA of this M-tile
            __threadfence();
            int b = m0 + tid;
            float s = g_part[0][b] + g_part[1][b] + g_part[2][b] +
                      g_part[3][b] + g_part[4][b];
            out[b] = fmaf(g_fm[b], Wout[0], bout[0] + s);
            if (tid == 0) {           // reset this tile's counters for replay
                g_cnt[by]  = 0;
                g_cnt1[by] = 0;
                g_gath[by] = 0;
            }
        }
    }
}

// ============================================================================
// Launch
// ============================================================================
extern "C" void kernel_launch(void* const* d_in, const int* in_sizes, int n_in,
                              void* d_out, int out_size) {
    const float* cont    = (const float*)d_in[0];
    const int*   cat     = (const int*)  d_in[1];
    const float* w_cont  = (const float*)d_in[2];
    const float* b_cont  = (const float*)d_in[3];
    const float* t_first = (const float*)d_in[4];
    const float* t_emb   = (const float*)d_in[5];
    const float* W1      = (const float*)d_in[6];
    const float* b1      = (const float*)d_in[7];
    const float* W2      = (const float*)d_in[8];
    const float* b2      = (const float*)d_in[9];
    const float* Wout    = (const float*)d_in[10];
    const float* bout    = (const float*)d_in[11];
    float* out = (float*)d_out;

    const int SMEM = 2 * STAGE_;   // 59904
    cudaFuncSetAttribute(megakernel, cudaFuncAttributeMaxDynamicSharedMemorySize, SMEM);

    // 1) weight transpose (coalesced both ways)
    prep_kernel<<<PREP_BLKS, 128>>>(W1, W2);

    // 2) gather + GEMM1 + GEMM2 + finish, dependency-pipelined in one launch
    megakernel<<<ALL_BLKS, 128, SMEM>>>(cont, cat, w_cont, b_cont, t_first, t_emb,
                                        b1, b2, Wout, bout, out);
}

// round 17
// speedup vs baseline: 1.0730x; 1.0730x over previous
#include <cuda_runtime.h>
#include <cuda_bf16.h>
#include <cuda_fp16.h>
#include <cstdint>

// ---------------- Problem constants ----------------
#define B_     16384
#define F_     26
#define V_     100000
#define E_     16
#define CONT_  13
#define K1_    429     // CONT_ + F_*E_
#define KP_    448     // padded K for BOTH GEMMs (mult of 64)
#define H_     400
#define NT_    80      // CTA N tile (5 * 80 = 400, exact)

// dnn_in layout (KP_): [ emb 0..415 | cont 416..428 | zero 429..447 ]
// h1 layout (KP_):     [ h1 0..399 | zero 400..447 ]  (pad never written; zero-init)

// ---------------- Scratch (device globals) ----------------
__device__ __align__(256) __half g_dnn [(size_t)B_ * KP_];
__device__ __align__(256) __half g_h1  [(size_t)B_ * KP_];
__device__ __align__(256) __half g_w1t [(size_t)H_ * KP_];
__device__ __align__(256) __half g_w2t [(size_t)H_ * KP_];
__device__ float g_fm  [B_];
__device__ float g_part[5][B_];
__device__ int   g_gath[B_ / 128];      // gather->GEMM1 tile readiness (self-reset)
__device__ int   g_cnt1[B_ / 128];      // GEMM1->GEMM2 tile readiness (self-reset)
__device__ int   g_cnt [B_ / 128];      // GEMM2 finish counter (self-reset)

// ---------------- PTX helpers ----------------
__device__ __forceinline__ uint32_t smem_u32(const void* p) {
    return (uint32_t)__cvta_generic_to_shared(p);
}
__device__ __forceinline__ int ld_acquire(const int* p) {
    int v;
    asm volatile("ld.acquire.gpu.global.s32 %0, [%1];" : "=r"(v) : "l"(p));
    return v;
}
#define CP16(dst_u32, src) \
    asm volatile("cp.async.cg.shared.global [%0], [%1], 16;" :: "r"(dst_u32), "l"(src))
#define CP_COMMIT() asm volatile("cp.async.commit_group;" ::: "memory")
#define CP_WAIT0()  asm volatile("cp.async.wait_group 0;" ::: "memory")
#define CP_WAIT1()  asm volatile("cp.async.wait_group 1;" ::: "memory")

#define LDSM_X4(r0, r1, r2, r3, addr)                                          \
    asm volatile("ldmatrix.sync.aligned.m8n8.x4.shared.b16 {%0,%1,%2,%3},[%4];"\
                 : "=r"(r0), "=r"(r1), "=r"(r2), "=r"(r3) : "r"(addr))
#define LDSM_X2(r0, r1, addr)                                                  \
    asm volatile("ldmatrix.sync.aligned.m8n8.x2.shared.b16 {%0,%1},[%2];"      \
                 : "=r"(r0), "=r"(r1) : "r"(addr))

__device__ __forceinline__ void mma_fp16(float* c,
                                         uint32_t a0, uint32_t a1, uint32_t a2, uint32_t a3,
                                         uint32_t b0, uint32_t b1) {
    asm volatile(
        "mma.sync.aligned.m16n8k16.row.col.f32.f16.f16.f32 "
        "{%0,%1,%2,%3},{%4,%5,%6,%7},{%8,%9},{%0,%1,%2,%3};"
        : "+f"(c[0]), "+f"(c[1]), "+f"(c[2]), "+f"(c[3])
        : "r"(a0), "r"(a1), "r"(a2), "r"(a3), "r"(b0), "r"(b1));
}

__device__ __forceinline__ uint32_t pack2(float a, float b) {
    __half h0 = __float2half_rn(a), h1 = __float2half_rn(b);
    return (uint32_t)__half_as_ushort(h0) | ((uint32_t)__half_as_ushort(h1) << 16);
}

// ============================================================================
// Prep (launch 1): tiled 32x32 smem transpose, coalesced read AND write.
// ============================================================================
#define KTILES_ 14   // 448/32
#define NTILES_ 13   // ceil(400/32)
#define PREP_BLKS (2 * KTILES_ * NTILES_)   // 364

__global__ void __launch_bounds__(128)
prep_kernel(const float* __restrict__ W1, const float* __restrict__ W2) {
    __shared__ float sm[32][33];
    int t = blockIdx.x;
    const bool m2 = (t >= KTILES_ * NTILES_);
    if (m2) t -= KTILES_ * NTILES_;
    const int kt = t % KTILES_, nt = t / KTILES_;
    const int tx = threadIdx.x & 31, ty = threadIdx.x >> 5;   // 32 x 4

    #pragma unroll
    for (int i = 0; i < 8; i++) {
        int k = kt * 32 + ty + i * 4;      // global padded-k
        int n = nt * 32 + tx;              // global n
        float v = 0.f;
        if (n < H_) {
            if (!m2) {
                if (k < 416)      v = W1[(size_t)(CONT_ + k) * H_ + n];
                else if (k < 429) v = W1[(size_t)(k - 416) * H_ + n];
            } else {
                if (k < H_)       v = W2[(size_t)k * H_ + n];
            }
        }
        sm[ty + i * 4][tx] = v;
    }
    __syncthreads();
    __half* dst = m2 ? g_w2t : g_w1t;
    #pragma unroll
    for (int i = 0; i < 8; i++) {
        int n = nt * 32 + ty + i * 4;
        int k = kt * 32 + tx;
        if (n < H_)
            dst[(size_t)n * KP_ + k] = __float2half_rn(sm[tx][ty + i * 4]);
    }
}

// ============================================================================
// Megakernel (launch 2): 1408 CTAs, 128 threads each.
//   bids [0,128)    : gather+FM, ONE BLOCK PER M-TILE, thread = sample
//                     (26 independent field loads/thread -> high MLP at low occ;
//                      FM fully thread-local, zero shuffles).
//   bids [128,768)  : GEMM1 (waits g_gath[by]==1): h1 = relu(dnn@W1+b1).
//   bids [768,1408) : GEMM2 (waits g_cnt1[by]==5): dot w/ Wout; finisher
//                     writes out and resets this tile's counters.
//   GEMM geometry: CTA 128x80, 4 warps, warp tile 64x40, BK=64, K=448.
// ============================================================================
#define ROWB_   144
#define OFFB_   (128 * ROWB_)
#define STAGE_  ((128 + NT_) * ROWB_)        // 29952
#define NKB_    7
#define GA_BLKS (B_ / 128)                   // 128
#define G1_OFF  GA_BLKS                      // 128
#define G2_OFF  (GA_BLKS + 5 * (B_ / 128))   // 768
#define ALL_BLKS (GA_BLKS + 10 * (B_ / 128)) // 1408

__global__ void __launch_bounds__(128)
megakernel(const float* __restrict__ cont, const int* __restrict__ cat,
           const float* __restrict__ w_cont, const float* __restrict__ b_cont,
           const float* __restrict__ t_first, const float* __restrict__ t_emb,
           const float* __restrict__ b1, const float* __restrict__ b2,
           const float* __restrict__ Wout, const float* __restrict__ bout,
           float* __restrict__ out) {
    constexpr int CPR = 8;
    constexpr int NCH = (128 + NT_) * CPR;   // 1664
    constexpr int NIT = NCH / 128;           // 13

    extern __shared__ char smem_raw[];
    __shared__ float part[2][128];
    __shared__ int   s_done;

    const int bid = blockIdx.x;
    const int tid = threadIdx.x;

    // ========================= GATHER region =========================
    if (bid < GA_BLKS) {
        const int b = bid * 128 + tid;     // this thread's sample
        float S[16];
        #pragma unroll
        for (int e = 0; e < 16; e++) S[e] = 0.f;
        float q = 0.f, scal = 0.f;

        __half* drow = g_dnn + (size_t)b * KP_;
        const int* crow = cat + (size_t)b * F_;

        #pragma unroll
        for (int f = 0; f < F_; f++) {
            int idx = crow[f];
            const float4* src =
                reinterpret_cast<const float4*>(t_emb + ((size_t)f * V_ + (size_t)idx) * E_);
            float4 r0 = src[0], r1 = src[1], r2 = src[2], r3 = src[3];
            uint4 u0 = make_uint4(pack2(r0.x, r0.y), pack2(r0.z, r0.w),
                                  pack2(r1.x, r1.y), pack2(r1.z, r1.w));
            uint4 u1 = make_uint4(pack2(r2.x, r2.y), pack2(r2.z, r2.w),
                                  pack2(r3.x, r3.y), pack2(r3.z, r3.w));
            reinterpret_cast<uint4*>(drow + f * E_)[0] = u0;
            reinterpret_cast<uint4*>(drow + f * E_)[1] = u1;

            S[0]+=r0.x; S[1]+=r0.y; S[2]+=r0.z; S[3]+=r0.w;
            S[4]+=r1.x; S[5]+=r1.y; S[6]+=r1.z; S[7]+=r1.w;
            S[8]+=r2.x; S[9]+=r2.y; S[10]+=r2.z; S[11]+=r2.w;
            S[12]+=r3.x; S[13]+=r3.y; S[14]+=r3.z; S[15]+=r3.w;
            q = fmaf(r0.x,r0.x,q); q = fmaf(r0.y,r0.y,q);
            q = fmaf(r0.z,r0.z,q); q = fmaf(r0.w,r0.w,q);
            q = fmaf(r1.x,r1.x,q); q = fmaf(r1.y,r1.y,q);
            q = fmaf(r1.z,r1.z,q); q = fmaf(r1.w,r1.w,q);
            q = fmaf(r2.x,r2.x,q); q = fmaf(r2.y,r2.y,q);
            q = fmaf(r2.z,r2.z,q); q = fmaf(r2.w,r2.w,q);
            q = fmaf(r3.x,r3.x,q); q = fmaf(r3.y,r3.y,q);
            q = fmaf(r3.z,r3.z,q); q = fmaf(r3.w,r3.w,q);
            scal += t_first[(size_t)f * V_ + (size_t)idx];
        }

        // cont cols 416..428 + zero pad 429..447, packed as 4 x uint4
        {
            const float* cr = cont + (size_t)b * CONT_;
            float c[13];
            #pragma unroll
            for (int i = 0; i < 13; i++) {
                c[i] = cr[i];
                scal = fmaf(c[i], w_cont[i], scal);
            }
            uint32_t pk[16];
            #pragma unroll
            for (int i = 0; i < 6; i++) pk[i] = pack2(c[2*i], c[2*i+1]);
            pk[6] = pack2(c[12], 0.f);
            #pragma unroll
            for (int i = 7; i < 16; i++) pk[i] = 0u;
            uint4* dst = reinterpret_cast<uint4*>(drow + 416);
            dst[0] = make_uint4(pk[0],  pk[1],  pk[2],  pk[3]);
            dst[1] = make_uint4(pk[4],  pk[5],  pk[6],  pk[7]);
            dst[2] = make_uint4(pk[8],  pk[9],  pk[10], pk[11]);
            dst[3] = make_uint4(pk[12], pk[13], pk[14], pk[15]);
        }

        float ss = 0.f;
        #pragma unroll
        for (int e = 0; e < 16; e++) ss = fmaf(S[e], S[e], ss);
        g_fm[b] = scal + b_cont[0] + 0.5f * (ss - q);

        __threadfence();
        __syncthreads();
        if (tid == 0) atomicAdd(&g_gath[bid], 1);
        return;
    }

    // ========================= GEMM region =========================
    const bool p2  = (bid >= G2_OFF);
    const int lbid = p2 ? bid - G2_OFF : bid - G1_OFF;
    const int by   = lbid / 5;
    const int bx   = lbid % 5;

    const __half* A    = p2 ? g_h1 : g_dnn;
    const __half* Bw   = p2 ? g_w2t : g_w1t;
    const float*  bias = p2 ? b2  : b1;

    const uint32_t sbase = smem_u32(smem_raw);
    const int warp = tid >> 5, lane = tid & 31;
    const int gr = lane >> 2, gc = lane & 3;
    const int wm  = (warp >> 1) * 64;
    const int wni = warp & 1;
    const int wn  = wni * 40;
    const int m0 = by * 128;
    const int n0 = bx * NT_;

    const int lane8 = lane & 7;
    const int laneH = (lane >> 3) & 1;
    const int laneK = lane >> 4;
    const uint32_t aoff  = (uint32_t)((wm + lane8 + laneH * 8) * ROWB_ + laneK * 16);
    const uint32_t boff4 = (uint32_t)((wn + lane8 + laneK * 8) * ROWB_ + laneH * 16);
    const uint32_t boff2 = (uint32_t)((wn + 32 + lane8) * ROWB_ + laneH * 16);

    // dependency wait
    if (tid == 0) {
        if (p2) { while (ld_acquire(&g_cnt1[by]) != 5) __nanosleep(64); }
        else    { while (ld_acquire(&g_gath[by]) != 1) __nanosleep(64); }
    }
    __syncthreads();

    float acc[4][5][4];
    #pragma unroll
    for (int i = 0; i < 4; i++)
        #pragma unroll
        for (int j = 0; j < 5; j++)
            #pragma unroll
            for (int k = 0; k < 4; k++) acc[i][j][k] = 0.f;

    #define LOAD_KB(KB, BUF)                                                        \
    do {                                                                            \
        const int k0_ = (KB) * 64;                                                  \
        const uint32_t st_ = sbase + (BUF) * STAGE_;                                \
        _Pragma("unroll")                                                           \
        for (int h = 0; h < NIT; h++) {                                             \
            int c_ = tid + h * 128;                                                 \
            int row_ = c_ / CPR, q_ = c_ % CPR;                                     \
            if (row_ < 128) {                                                       \
                CP16(st_ + row_ * ROWB_ + q_ * 16,                                  \
                     A + (size_t)(m0 + row_) * KP_ + k0_ + q_ * 8);                 \
            } else {                                                                \
                int r2_ = row_ - 128;                                               \
                CP16(st_ + OFFB_ + r2_ * ROWB_ + q_ * 16,                           \
                     Bw + (size_t)(n0 + r2_) * KP_ + k0_ + q_ * 8);                 \
            }                                                                       \
        }                                                                           \
    } while (0)

    LOAD_KB(0, 0);
    CP_COMMIT();

    for (int kb = 0; kb < NKB_; kb++) {
        const int buf = kb & 1;
        if (kb + 1 < NKB_) { LOAD_KB(kb + 1, buf ^ 1); CP_COMMIT(); CP_WAIT1(); }
        else               { CP_WAIT0(); }
        __syncthreads();

        const uint32_t st = sbase + buf * STAGE_;
        #pragma unroll
        for (int ks = 0; ks < 4; ks++) {
            const uint32_t ko = ks * 32;
            uint32_t ah[4][4], bh[5][2];
            #pragma unroll
            for (int mi = 0; mi < 4; mi++) {
                uint32_t ad = st + aoff + mi * (16 * ROWB_) + ko;
                LDSM_X4(ah[mi][0], ah[mi][1], ah[mi][2], ah[mi][3], ad);
            }
            #pragma unroll
            for (int nj = 0; nj < 2; nj++) {
                uint32_t bd = st + OFFB_ + boff4 + nj * (16 * ROWB_) + ko;
                LDSM_X4(bh[nj*2][0], bh[nj*2][1], bh[nj*2+1][0], bh[nj*2+1][1], bd);
            }
            LDSM_X2(bh[4][0], bh[4][1], st + OFFB_ + boff2 + ko);

            #pragma unroll
            for (int mi = 0; mi < 4; mi++)
                #pragma unroll
                for (int ni = 0; ni < 5; ni++)
                    mma_fp16(acc[mi][ni], ah[mi][0], ah[mi][1], ah[mi][2], ah[mi][3],
                             bh[ni][0], bh[ni][1]);
        }
        __syncthreads();
    }
    #undef LOAD_KB

    if (!p2) {
        // ---- GEMM1 epilogue: relu(+bias) -> h1 fp16 ----
        #pragma unroll
        for (int mi = 0; mi < 4; mi++) {
            int r = m0 + wm + mi * 16 + gr;
            #pragma unroll
            for (int ni = 0; ni < 5; ni++) {
                int n = n0 + wn + ni * 8 + gc * 2;
                float b0v = bias[n], b1v = bias[n + 1];
                #pragma unroll
                for (int half = 0; half < 2; half++) {
                    float x0 = fmaxf(acc[mi][ni][half * 2 + 0] + b0v, 0.f);
                    float x1 = fmaxf(acc[mi][ni][half * 2 + 1] + b1v, 0.f);
                    size_t o = (size_t)(r + half * 8) * KP_ + n;
                    *reinterpret_cast<uint32_t*>(g_h1 + o) = pack2(x0, x1);
                }
            }
        }
        __threadfence();
        __syncthreads();
        if (tid == 0) atomicAdd(&g_cnt1[by], 1);
    } else {
        // ---- GEMM2 epilogue: dot with Wout; finisher writes out ----
        #pragma unroll
        for (int mi = 0; mi < 4; mi++) {
            float s0 = 0.f, s1 = 0.f;
            #pragma unroll
            for (int ni = 0; ni < 5; ni++) {
                int n = n0 + wn + ni * 8 + gc * 2;
                float w0v = Wout[1 + n], w1v = Wout[2 + n];
                float b0v = bias[n],     b1v = bias[n + 1];
                s0 = fmaf(fmaxf(acc[mi][ni][0] + b0v, 0.f), w0v, s0);
                s0 = fmaf(fmaxf(acc[mi][ni][1] + b1v, 0.f), w1v, s0);
                s1 = fmaf(fmaxf(acc[mi][ni][2] + b0v, 0.f), w0v, s1);
                s1 = fmaf(fmaxf(acc[mi][ni][3] + b1v, 0.f), w1v, s1);
            }
            s0 += __shfl_xor_sync(0xffffffffu, s0, 1);
            s0 += __shfl_xor_sync(0xffffffffu, s0, 2);
            s1 += __shfl_xor_sync(0xffffffffu, s1, 1);
            s1 += __shfl_xor_sync(0xffffffffu, s1, 2);
            if (gc == 0) {
                part[wni][wm + mi * 16 + gr]     = s0;
                part[wni][wm + mi * 16 + gr + 8] = s1;
            }
        }
        __syncthreads();
        g_part[bx][m0 + tid] = part[0][tid] + part[1][tid];
        __threadfence();
        __syncthreads();
        if (tid == 0) s_done = atomicAdd(&g_cnt[by], 1);
        __syncthreads();
        if (s_done == 4) {            // last GEMM2 CTA of this M-tile
            __threadfence();
            int b = m0 + tid;
            float s = g_part[0][b] + g_part[1][b] + g_part[2][b] +
                      g_part[3][b] + g_part[4][b];
            out[b] = fmaf(g_fm[b], Wout[0], bout[0] + s);
            if (tid == 0) {           // reset this tile's counters for replay
                g_cnt[by]  = 0;
                g_cnt1[by] = 0;
                g_gath[by] = 0;
            }
        }
    }
}

// ============================================================================
// Launch
// ============================================================================
extern "C" void kernel_launch(void* const* d_in, const int* in_sizes, int n_in,
                              void* d_out, int out_size) {
    const float* cont    = (const float*)d_in[0];
    const int*   cat     = (const int*)  d_in[1];
    const float* w_cont  = (const float*)d_in[2];
    const float* b_cont  = (const float*)d_in[3];
    const float* t_first = (const float*)d_in[4];
    const float* t_emb   = (const float*)d_in[5];
    const float* W1      = (const float*)d_in[6];
    const float* b1      = (const float*)d_in[7];
    const float* W2      = (const float*)d_in[8];
    const float* b2      = (const float*)d_in[9];
    const float* Wout    = (const float*)d_in[10];
    const float* bout    = (const float*)d_in[11];
    float* out = (float*)d_out;

    const int SMEM = 2 * STAGE_;   // 59904
    cudaFuncSetAttribute(megakernel, cudaFuncAttributeMaxDynamicSharedMemorySize, SMEM);

    // 1) weight transpose (coalesced both ways)
    prep_kernel<<<PREP_BLKS, 128>>>(W1, W2);

    // 2) gather + GEMM1 + GEMM2 + finish, dependency-pipelined in one launch
    megakernel<<<ALL_BLKS, 128, SMEM>>>(cont, cat, w_cont, b_cont, t_first, t_emb,
                                        b1, b2, Wout, bout, out);
}